// round 14
// baseline (speedup 1.0000x reference)
#include <cuda_runtime.h>
#include <cuda_bf16.h>
#include <math.h>
#include <stdint.h>

// ---------------- Problem constants ----------------
#define NE 256
#define KH 7168
#define MAX_T 16384
#define TOPK_GROUP 4
#define TOP_K 8
#define ROUTED_SCALE 2.5f
#define N_GROUP 8

#define TAU_E 3e-5f
#define TAU_G 1e-4f

// ---------------- GEMM config ----------------
#define BM 64
#define BN 128
#define NCH_ST (KH / 32)        // 224 stages of K=32
// smem stage layout (bytes)
#define AHI_OFF 0
#define ALO_OFF 5120            // 64 rows * 80 B
#define BHI_OFF 10240
#define BLO_OFF 18944           // +16*272*2
#define STAGE   27648
#define NSTAGE  2
#define SMEM_TOTAL (NSTAGE * STAGE)   // 55296 -> 3 CTAs/SM (regs permitting)

// ---------------- device scratch ----------------
__device__ float g_logits[MAX_T * NE];
__device__ __nv_bfloat16 g_bhi[KH * NE];
__device__ __nv_bfloat16 g_blo[KH * NE];
__device__ int g_list[MAX_T];
__device__ int g_count;

// ---------------- helpers ----------------
__device__ __forceinline__ uint32_t smem_u32(const void* p) {
    uint32_t a;
    asm("{ .reg .u64 t; cvta.to.shared.u64 t, %1; cvt.u32.u64 %0, t; }" : "=r"(a) : "l"(p));
    return a;
}
__device__ __forceinline__ void cpa16(uint32_t dst, const void* src) {
    asm volatile("cp.async.cg.shared.global [%0], [%1], 16;" :: "r"(dst), "l"(src));
}
__device__ __forceinline__ void ldsm_x4(uint32_t* r, uint32_t addr) {
    asm volatile("ldmatrix.sync.aligned.m8n8.x4.shared.b16 {%0,%1,%2,%3}, [%4];"
                 : "=r"(r[0]), "=r"(r[1]), "=r"(r[2]), "=r"(r[3]) : "r"(addr));
}
__device__ __forceinline__ void ldsm_x4t(uint32_t* r, uint32_t addr) {
    asm volatile("ldmatrix.sync.aligned.m8n8.x4.trans.shared.b16 {%0,%1,%2,%3}, [%4];"
                 : "=r"(r[0]), "=r"(r[1]), "=r"(r[2]), "=r"(r[3]) : "r"(addr));
}
__device__ __forceinline__ void mma_bf16(float* c, const uint32_t* a, const uint32_t* b) {
    asm volatile("mma.sync.aligned.m16n8k16.row.col.f32.bf16.bf16.f32 "
                 "{%0,%1,%2,%3}, {%4,%5,%6,%7}, {%8,%9}, {%0,%1,%2,%3};"
                 : "+f"(c[0]), "+f"(c[1]), "+f"(c[2]), "+f"(c[3])
                 : "r"(a[0]), "r"(a[1]), "r"(a[2]), "r"(a[3]), "r"(b[0]), "r"(b[1]));
}

// ---------------- split B: [K,N] fp32 -> bf16 hi/lo (also resets g_count) ----
__global__ __launch_bounds__(256)
void split_b_kernel(const float* __restrict__ B,
                    __nv_bfloat16* __restrict__ bhi,
                    __nv_bfloat16* __restrict__ blo)
{
    if (blockIdx.x == 0 && threadIdx.x == 0) g_count = 0;
    const int idx = blockIdx.x * 256 + threadIdx.x;
    if (idx >= KH * NE) return;
    const float v = B[idx];
    const __nv_bfloat16 h = __float2bfloat16(v);
    bhi[idx] = h;
    blo[idx] = __float2bfloat16(v - __bfloat162float(h));
}

// ---------------- GEMM: fused A-convert, 3-term split-bf16, occ-3 ------------
__global__ __launch_bounds__(256, 3)
void gate_gemm_mma(const float* __restrict__ A,
                   const __nv_bfloat16* __restrict__ Bhi,
                   const __nv_bfloat16* __restrict__ Blo,
                   float* __restrict__ C)
{
    extern __shared__ char smem[];
    const uint32_t sb = smem_u32(smem);
    const int tid = threadIdx.x;
    const int wid = tid >> 5, lane = tid & 31;
    const int Mbase = blockIdx.y * BM, Nbase = blockIdx.x * BN;
    const int mw = (wid & 1) * 32;        // 2 M-warps
    const int nw = (wid >> 1) * 32;       // 4 N-warps

    const int l7 = lane & 7, l8 = (lane >> 3) & 1, l16 = lane >> 4;
    uint32_t a_rel[2];
    #pragma unroll
    for (int tm = 0; tm < 2; ++tm)
        a_rel[tm] = (uint32_t)((mw + 16 * tm + l7 + 8 * l8) * 80 + l16 * 16);
    const int q = lane >> 3;
    uint32_t b4_rel[2];
    #pragma unroll
    for (int tn2 = 0; tn2 < 2; ++tn2)
        b4_rel[tn2] = (uint32_t)((l7 + 8 * (q & 1)) * 272 +
                                 (nw + 8 * (2 * tn2 + (q >> 1))) * 2);

    // A LDG: 64 rows x 8 float4-chunks = 512 -> 2 per thread (rows ar0, ar0+32)
    const int ar0 = tid >> 3, ac8 = tid & 7;
    const float* Aptr = A + (size_t)(Mbase + ar0) * KH + ac8 * 4;
    const uint32_t a_sts0 = (uint32_t)(ar0 * 80 + ac8 * 8);
    // B cp.async coords
    const int bk0 = tid >> 4, bch = tid & 15;

    float4 pa[2];
    auto ldgA = [&](int c) {
        const int kb = c * 32;
        #pragma unroll
        for (int h = 0; h < 2; ++h)
            pa[h] = *(const float4*)(Aptr + (size_t)(h * 32) * KH + kb);
    };
    auto stsA = [&](int s) {
        char* buf = smem + s * STAGE;
        #pragma unroll
        for (int h = 0; h < 2; ++h) {
            const float4 v = pa[h];
            __nv_bfloat162 h01 = __floats2bfloat162_rn(v.x, v.y);
            __nv_bfloat162 h23 = __floats2bfloat162_rn(v.z, v.w);
            __nv_bfloat162 l01 = __floats2bfloat162_rn(v.x - __bfloat162float(h01.x),
                                                       v.y - __bfloat162float(h01.y));
            __nv_bfloat162 l23 = __floats2bfloat162_rn(v.z - __bfloat162float(h23.x),
                                                       v.w - __bfloat162float(h23.y));
            uint2 hv, lv;
            hv.x = *(uint32_t*)&h01; hv.y = *(uint32_t*)&h23;
            lv.x = *(uint32_t*)&l01; lv.y = *(uint32_t*)&l23;
            const uint32_t off = a_sts0 + (uint32_t)(h * 32 * 80);
            *(uint2*)(buf + AHI_OFF + off) = hv;
            *(uint2*)(buf + ALO_OFF + off) = lv;
        }
    };
    auto issueB = [&](int c, int s) {
        const uint32_t buf = sb + (uint32_t)(s * STAGE);
        const int kb = c * 32;
        #pragma unroll
        for (int h = 0; h < 2; ++h) {
            const int kk = bk0 + h * 16;
            const size_t bsrc = (size_t)(kb + kk) * NE + Nbase + bch * 8;
            cpa16(buf + BHI_OFF + kk * 272 + bch * 16, Bhi + bsrc);
            cpa16(buf + BLO_OFF + kk * 272 + bch * 16, Blo + bsrc);
        }
    };

    float acc[2][4][4];
    #pragma unroll
    for (int i = 0; i < 2; ++i)
        #pragma unroll
        for (int j = 0; j < 4; ++j)
            #pragma unroll
            for (int k = 0; k < 4; ++k) acc[i][j][k] = 0.0f;

    // prologue: stage 0 resident, A(1) in regs, B(0) in flight
    ldgA(0); stsA(0); ldgA(1);
    issueB(0, 0); asm volatile("cp.async.commit_group;" ::: "memory");

    int s = 0;
    for (int c = 0; c < NCH_ST; ++c) {
        asm volatile("cp.async.wait_group 0;" ::: "memory");
        __syncthreads();
        const uint32_t stg = sb + (uint32_t)(s * STAGE);

        if (c + 1 < NCH_ST) {
            const int s1 = s ^ 1;
            stsA(s1);                 // A(c+1) regs -> other buffer
            issueB(c + 1, s1);        // B(c+1) async into other buffer
            asm volatile("cp.async.commit_group;" ::: "memory");
        }
        if (c + 2 < NCH_ST) ldgA(c + 2);

        #pragma unroll
        for (int ks = 0; ks < 2; ++ks) {
            uint32_t ah[2][4], al[2][4];
            #pragma unroll
            for (int tm = 0; tm < 2; ++tm) {
                ldsm_x4(ah[tm], stg + AHI_OFF + a_rel[tm] + ks * 32);
                ldsm_x4(al[tm], stg + ALO_OFF + a_rel[tm] + ks * 32);
            }
            #pragma unroll
            for (int tn2 = 0; tn2 < 2; ++tn2) {
                uint32_t bh4[4], bl4[4];
                ldsm_x4t(bh4, stg + BHI_OFF + b4_rel[tn2] + ks * 4352);
                ldsm_x4t(bl4, stg + BLO_OFF + b4_rel[tn2] + ks * 4352);
                #pragma unroll
                for (int half = 0; half < 2; ++half) {
                    const int tn = 2 * tn2 + half;
                    #pragma unroll
                    for (int tm = 0; tm < 2; ++tm) {
                        mma_bf16(acc[tm][tn], ah[tm], bh4 + 2 * half);
                        mma_bf16(acc[tm][tn], al[tm], bh4 + 2 * half);
                        mma_bf16(acc[tm][tn], ah[tm], bl4 + 2 * half);
                    }
                }
            }
        }
        s ^= 1;
    }

    #pragma unroll
    for (int tm = 0; tm < 2; ++tm) {
        const int r0 = Mbase + mw + 16 * tm + (lane >> 2);
        #pragma unroll
        for (int tn = 0; tn < 4; ++tn) {
            const int cc = Nbase + nw + 8 * tn + 2 * (lane & 3);
            float2 v0, v1;
            v0.x = acc[tm][tn][0]; v0.y = acc[tm][tn][1];
            v1.x = acc[tm][tn][2]; v1.y = acc[tm][tn][3];
            *(float2*)&C[(size_t)r0 * NE + cc] = v0;
            *(float2*)&C[(size_t)(r0 + 8) * NE + cc] = v1;
        }
    }
}

// ---------------- pass 1: route + margin detection ----------------
__global__ __launch_bounds__(256)
void route_pass1(const float* __restrict__ logits,
                 const float* __restrict__ bias,
                 float* __restrict__ out_idx,
                 float* __restrict__ out_w,
                 int* __restrict__ list,
                 int T)
{
    const int gwarp = (blockIdx.x * blockDim.x + threadIdx.x) >> 5;
    const int lane = threadIdx.x & 31;
    if (gwarp >= T) return;

    const float* lp = logits + (size_t)gwarp * NE;

    float s[8];
    #pragma unroll
    for (int j = 0; j < 8; ++j) {
        const int e = lane * 8 + j;
        s[j] = 1.0f / (1.0f + expf(-lp[e])) + bias[e];
    }

    float m1 = -1e30f, m2 = -1e30f;
    #pragma unroll
    for (int j = 0; j < 8; ++j) {
        const float v = s[j];
        if (v > m1) { m2 = m1; m1 = v; }
        else if (v > m2) { m2 = v; }
    }
    #pragma unroll
    for (int off = 1; off < 4; off <<= 1) {
        const float o1 = __shfl_xor_sync(0xffffffffu, m1, off);
        const float o2 = __shfl_xor_sync(0xffffffffu, m2, off);
        const float n1 = fmaxf(m1, o1);
        const float n2 = fmaxf(fminf(m1, o1), fmaxf(m2, o2));
        m1 = n1; m2 = n2;
    }
    const float gscore = m1 + m2;

    float gs[N_GROUP];
    #pragma unroll
    for (int g = 0; g < N_GROUP; ++g)
        gs[g] = __shfl_sync(0xffffffffu, gscore, g * 4);

    unsigned gmask = 0;
    float g4 = 0.0f, g5 = 0.0f;
    #pragma unroll
    for (int t = 0; t < 5; ++t) {
        int best = 0; float bv = -1e30f;
        #pragma unroll
        for (int g = 0; g < N_GROUP; ++g)
            if (!((gmask >> g) & 1u) && gs[g] > bv) { bv = gs[g]; best = g; }
        if (t < 4) { gmask |= 1u << best; if (t == 3) g4 = bv; }
        else g5 = bv;
    }
    bool flag = (g4 - g5) < TAU_G;

    const bool sel = (gmask >> (lane >> 2)) & 1u;
    float mv[8];
    #pragma unroll
    for (int j = 0; j < 8; ++j) mv[j] = sel ? s[j] : 0.0f;

    bool used[8];
    #pragma unroll
    for (int j = 0; j < 8; ++j) used[j] = false;

    float my_v = 0.0f; int my_i = 0; float vsum = 0.0f;
    float prev = 0.0f;
    #pragma unroll
    for (int t = 0; t < TOP_K + 1; ++t) {
        float bv = -1e30f; int bi = NE;
        #pragma unroll
        for (int j = 0; j < 8; ++j) {
            if (!used[j]) {
                const float v = mv[j];
                const int e = lane * 8 + j;
                if (v > bv || (v == bv && e < bi)) { bv = v; bi = e; }
            }
        }
        #pragma unroll
        for (int off = 16; off > 0; off >>= 1) {
            const float ov = __shfl_xor_sync(0xffffffffu, bv, off);
            const int   oi = __shfl_xor_sync(0xffffffffu, bi, off);
            if (ov > bv || (ov == bv && oi < bi)) { bv = ov; bi = oi; }
        }
        if (t > 0) flag = flag || ((prev - bv) < TAU_E);
        prev = bv;
        if (t < TOP_K) {
            if ((bi >> 3) == lane) used[bi & 7] = true;
            if (lane == t) { my_v = bv; my_i = bi; }
            vsum += bv;
        }
    }

    const float scale = ROUTED_SCALE / (vsum + 1e-20f);
    if (lane < TOP_K) {
        out_idx[(size_t)gwarp * TOP_K + lane] = (float)my_i;
        out_w  [(size_t)gwarp * TOP_K + lane] = my_v * scale;
    }
    if (flag && lane == 0) {
        const int p = atomicAdd(&g_count, 1);
        if (p < MAX_T) list[p] = gwarp;
    }
}

// ------- fused fallback: exact fp32 logits + re-route, grid-stride ------------
__global__ __launch_bounds__(256)
void fb_route(const float* __restrict__ A,
              const float* __restrict__ B,
              const float* __restrict__ bias,
              float* __restrict__ out_idx,
              float* __restrict__ out_w,
              const int* __restrict__ list)
{
    __shared__ float As[KH];
    __shared__ float sc[NE];
    const int tid = threadIdx.x;
    const int count = g_count;

    for (int w = blockIdx.x; w < count; w += gridDim.x) {
        const int token = list[w];
        {
            const float* arow = A + (size_t)token * KH;
            #pragma unroll
            for (int i = 0; i < KH / 4 / 256; ++i) {
                const int k4 = i * 256 + tid;
                *(float4*)&As[k4 * 4] = *(const float4*)(arow + k4 * 4);
            }
        }
        __syncthreads();

        {
            float acc = 0.0f;
            #pragma unroll 16
            for (int k = 0; k < KH; ++k)
                acc = fmaf(As[k], B[(size_t)k * NE + tid], acc);
            sc[tid] = 1.0f / (1.0f + expf(-acc)) + bias[tid];
        }
        __syncthreads();

        if (tid < 32) {
            const int lane = tid;
            float s[8];
            #pragma unroll
            for (int j = 0; j < 8; ++j) s[j] = sc[lane * 8 + j];

            float m1 = -1e30f, m2 = -1e30f;
            #pragma unroll
            for (int j = 0; j < 8; ++j) {
                const float v = s[j];
                if (v > m1) { m2 = m1; m1 = v; }
                else if (v > m2) { m2 = v; }
            }
            #pragma unroll
            for (int off = 1; off < 4; off <<= 1) {
                const float o1 = __shfl_xor_sync(0xffffffffu, m1, off);
                const float o2 = __shfl_xor_sync(0xffffffffu, m2, off);
                const float n1 = fmaxf(m1, o1);
                const float n2 = fmaxf(fminf(m1, o1), fmaxf(m2, o2));
                m1 = n1; m2 = n2;
            }
            const float gscore = m1 + m2;

            float gs[N_GROUP];
            #pragma unroll
            for (int g = 0; g < N_GROUP; ++g)
                gs[g] = __shfl_sync(0xffffffffu, gscore, g * 4);

            unsigned gmask = 0;
            #pragma unroll
            for (int t = 0; t < TOPK_GROUP; ++t) {
                int best = 0; float bv = -1e30f;
                #pragma unroll
                for (int g = 0; g < N_GROUP; ++g)
                    if (!((gmask >> g) & 1u) && gs[g] > bv) { bv = gs[g]; best = g; }
                gmask |= 1u << best;
            }

            const bool sel = (gmask >> (lane >> 2)) & 1u;
            float mv[8];
            #pragma unroll
            for (int j = 0; j < 8; ++j) mv[j] = sel ? s[j] : 0.0f;

            bool used[8];
            #pragma unroll
            for (int j = 0; j < 8; ++j) used[j] = false;

            float my_v = 0.0f; int my_i = 0; float vsum = 0.0f;
            #pragma unroll
            for (int t = 0; t < TOP_K; ++t) {
                float bv = -1e30f; int bi = NE;
                #pragma unroll
                for (int j = 0; j < 8; ++j) {
                    if (!used[j]) {
                        const float v = mv[j];
                        const int e = lane * 8 + j;
                        if (v > bv || (v == bv && e < bi)) { bv = v; bi = e; }
                    }
                }
                #pragma unroll
                for (int off = 16; off > 0; off >>= 1) {
                    const float ov = __shfl_xor_sync(0xffffffffu, bv, off);
                    const int   oi = __shfl_xor_sync(0xffffffffu, bi, off);
                    if (ov > bv || (ov == bv && oi < bi)) { bv = ov; bi = oi; }
                }
                if ((bi >> 3) == lane) used[bi & 7] = true;
                if (lane == t) { my_v = bv; my_i = bi; }
                vsum += bv;
            }

            const float scale = ROUTED_SCALE / (vsum + 1e-20f);
            if (lane < TOP_K) {
                out_idx[(size_t)token * TOP_K + lane] = (float)my_i;
                out_w  [(size_t)token * TOP_K + lane] = my_v * scale;
            }
        }
        __syncthreads();
    }
}

// ---------------- launch ----------------
extern "C" void kernel_launch(void* const* d_in, const int* in_sizes, int n_in,
                              void* d_out, int out_size)
{
    const float* hs   = (const float*)d_in[0];
    const float* wk   = (const float*)d_in[1];
    const float* bias = (const float*)d_in[2];

    const int T = in_sizes[0] / KH;   // 16384

    float* logits;      cudaGetSymbolAddress((void**)&logits, g_logits);
    __nv_bfloat16 *bhi, *blo;
    cudaGetSymbolAddress((void**)&bhi, g_bhi);
    cudaGetSymbolAddress((void**)&blo, g_blo);
    int* list;          cudaGetSymbolAddress((void**)&list, g_list);

    float* out_f = (float*)d_out;
    float* out_idx = out_f;
    float* out_w   = out_f + (size_t)T * TOP_K;

    split_b_kernel<<<(KH * NE + 255) / 256, 256>>>(wk, bhi, blo);

    cudaFuncSetAttribute(gate_gemm_mma, cudaFuncAttributeMaxDynamicSharedMemorySize, SMEM_TOTAL);
    dim3 grid(NE / BN, T / BM);
    gate_gemm_mma<<<grid, 256, SMEM_TOTAL>>>(hs, bhi, blo, logits);

    route_pass1<<<(T + 7) / 8, 256>>>(logits, bias, out_idx, out_w, list, T);
    fb_route<<<1024, 256>>>(hs, wk, bias, out_idx, out_w, list);
}